// round 13
// baseline (speedup 1.0000x reference)
#include <cuda_runtime.h>
#include <cuda_fp16.h>

#define NN 100000
#define EE 3200000
#define GG 512
#define HH 64
#define BN_EPS 1e-5f
#define DCAP 128    // per-node neighbor bucket capacity (P(deg>128) < 1e-40 for Poisson(32))
#define WPITCH 88   // smem row pitch in halves: 176B = 16B-aligned, 12-bank shift/row

typedef unsigned long long u64;

// ---------------- scratch (static __device__ — no allocation) ----------------
__device__ __align__(16) float  g_x4[NN * 4];       // padded input features [N][4]
__device__ __align__(16) __half g_xh[NN * 64];      // post-BN activations, fp16 [N][64]
__device__ __align__(16) __half g_aggh[NN * 64];    // agg, fp16; layer0 uses [N][16]
__device__ __align__(16) float  g_h[NN * 64];       // pre-BN MLP output (fp32)
__device__ __align__(16) __half g_w1ph[16 * 64];    // layer-0 W1 padded 3->16 rows, fp16
__device__ float g_stats[3 * 128];                  // per-layer: [0:64) sum, [64:128) sumsq
__device__ __align__(16) float g_pool[GG * 64];     // graph feature sums
__device__ float g_cnt[GG];                         // graph node counts
// bucket CSR
__device__ int g_cur[NN];                           // per-node fill count (== degree)
__device__ int g_srcs[NN * DCAP];                   // neighbor lists, bucketed

// vector RED (sm_90+): global float4 add, no return
__device__ __forceinline__ void red_add_v4(float* p, float4 v) {
    asm volatile("red.global.add.v4.f32 [%0], {%1,%2,%3,%4};"
                 :: "l"(p), "f"(v.x), "f"(v.y), "f"(v.z), "f"(v.w) : "memory");
}

// packed f32x2 helpers
__device__ __forceinline__ u64 pk2(float lo, float hi) {
    u64 r; asm("mov.b64 %0, {%1,%2};" : "=l"(r) : "f"(lo), "f"(hi)); return r;
}
__device__ __forceinline__ u64 add2(u64 a, u64 b) {
    u64 d; asm("add.rn.f32x2 %0, %1, %2;" : "=l"(d) : "l"(a), "l"(b)); return d;
}
__device__ __forceinline__ float2 upk(u64 v) {
    float2 f; asm("mov.b64 {%0,%1}, %2;" : "=f"(f.x), "=f"(f.y) : "l"(v)); return f;
}
__device__ __forceinline__ u64 h2f2(unsigned h) {
    __half2 hh = *reinterpret_cast<__half2*>(&h);
    float2 f = __half22float2(hh);
    return pk2(f.x, f.y);
}
__device__ __forceinline__ unsigned f22h2(float a, float b) {
    __half2 h = __floats2half2_rn(a, b);
    return *reinterpret_cast<unsigned*>(&h);
}
__device__ __forceinline__ u64 shfl_dn64(u64 v, int off) {
    return __shfl_down_sync(0xffffffffu, v, off);
}

// ---------------- tensor-core primitives ----------------
__device__ __forceinline__ unsigned sptr(const void* p) {
    return (unsigned)__cvta_generic_to_shared(p);
}
__device__ __forceinline__ void ldsm_x4(unsigned* r, unsigned addr) {
    asm volatile("ldmatrix.sync.aligned.m8n8.x4.shared.b16 {%0,%1,%2,%3}, [%4];"
                 : "=r"(r[0]), "=r"(r[1]), "=r"(r[2]), "=r"(r[3]) : "r"(addr));
}
__device__ __forceinline__ void ldsm_x2t(unsigned* r, unsigned addr) {
    asm volatile("ldmatrix.sync.aligned.m8n8.x2.trans.shared.b16 {%0,%1}, [%2];"
                 : "=r"(r[0]), "=r"(r[1]) : "r"(addr));
}
__device__ __forceinline__ void mma16816(float* c, const unsigned* a, const unsigned* b) {
    asm volatile("mma.sync.aligned.m16n8k16.row.col.f32.f16.f16.f32 "
                 "{%0,%1,%2,%3}, {%4,%5,%6,%7}, {%8,%9}, {%0,%1,%2,%3};"
                 : "+f"(c[0]), "+f"(c[1]), "+f"(c[2]), "+f"(c[3])
                 : "r"(a[0]), "r"(a[1]), "r"(a[2]), "r"(a[3]), "r"(b[0]), "r"(b[1]));
}

// ---------------- init: zero counters + pad W1 + zero layer0 agg tail ----------------
__global__ void k_init(const float* __restrict__ w1_0) {
    int i = blockIdx.x * blockDim.x + threadIdx.x;
    if (i < NN) {
        g_cur[i] = 0;
        uint4 z = make_uint4(0, 0, 0, 0);
        *reinterpret_cast<uint4*>(&g_aggh[i * 16]) = z;       // layer-0 cols 0..7
        *reinterpret_cast<uint4*>(&g_aggh[i * 16 + 8]) = z;   // layer-0 cols 8..15
    }
    if (i < GG * 64) g_pool[i] = 0.f;
    if (i < GG) g_cnt[i] = 0.f;
    if (i < 3 * 128) g_stats[i] = 0.f;
    if (i < 16 * 64) {
        int k = i >> 6, f = i & 63;
        g_w1ph[i] = __float2half((k < 3) ? w1_0[k * 64 + f] : 0.f);
    }
}

__global__ void k_prep(const float* __restrict__ x, const int* __restrict__ batch) {
    int n = blockIdx.x * blockDim.x + threadIdx.x;
    if (n < NN) {
        float4 v;
        v.x = x[n * 3 + 0];
        v.y = x[n * 3 + 1];
        v.z = x[n * 3 + 2];
        v.w = 0.f;
        reinterpret_cast<float4*>(g_x4)[n] = v;
        atomicAdd(&g_cnt[batch[n]], 1.0f);   // sorted batch -> REDUX aggregation
    }
}

// ---------------- one-pass bucket fill ----------------
__global__ void k_scatter(const int* __restrict__ ei) {
    int e = blockIdx.x * blockDim.x + threadIdx.x;
    if (e < EE) {
        int s = ei[e];
        int d = ei[EE + e];
        int p = atomicAdd(&g_cur[d], 1);
        if (p < DCAP) g_srcs[d * DCAP + p] = s;   // clamp: impossible-case safety
    }
}

// ---------------- gather aggregation (buckets, no atomics) ----------------
// layer 0: warp per node, LANE PER EDGE — 32 row loads in flight per warp.
__global__ void k_gather4() {
    int w = (blockIdx.x * blockDim.x + threadIdx.x) >> 5;
    if (w >= NN) return;
    int lane = threadIdx.x & 31;
    int beg = w * DCAP;
    int end = beg + min(g_cur[w], DCAP);
    u64 a01 = 0ull, a23 = 0ull;
    for (int j = beg + lane; j < end; j += 32) {
        int s = g_srcs[j];
        float4 v = reinterpret_cast<const float4*>(g_x4)[s];
        a01 = add2(a01, pk2(v.x, v.y));
        a23 = add2(a23, pk2(v.z, v.w));
    }
    #pragma unroll
    for (int off = 16; off > 0; off >>= 1) {
        a01 = add2(a01, shfl_dn64(a01, off));
        a23 = add2(a23, shfl_dn64(a23, off));
    }
    if (lane == 0) {
        float4 sv = reinterpret_cast<const float4*>(g_x4)[w];   // self term
        float2 f01 = upk(a01), f23 = upk(a23);
        uint2 o;
        o.x = f22h2(sv.x + f01.x, sv.y + f01.y);
        o.y = f22h2(sv.z + f23.x, sv.w + f23.y);
        *reinterpret_cast<uint2*>(&g_aggh[w * 16]) = o;
    }
}

// layers 1..2: warp per node; lane = r(0..7) chunk + q(0..3) edge slot.
// Unrolled x2: two accumulator sets (slots q, q+4) + idx prefetch -> 8 edges in flight.
__global__ void k_gather64() {
    int w = (blockIdx.x * blockDim.x + threadIdx.x) >> 5;
    if (w >= NN) return;
    int lane = threadIdx.x & 31;
    int r = lane & 7;    // uint4 chunk within 128B row
    int q = lane >> 3;   // edge slot 0..3
    int beg = w * DCAP;
    int end = beg + min(g_cur[w], DCAP);
    const uint4* __restrict__ rows = reinterpret_cast<const uint4*>(g_xh);  // 8 per row

    u64 a0 = 0ull, a1 = 0ull, a2 = 0ull, a3 = 0ull;   // slot set A (edges q + 8k)
    u64 b0 = 0ull, b1 = 0ull, b2 = 0ull, b3 = 0ull;   // slot set B (edges q+4 + 8k)
    if (q == 0) {  // self term
        uint4 v = rows[w * 8 + r];
        a0 = h2f2(v.x); a1 = h2f2(v.y); a2 = h2f2(v.z); a3 = h2f2(v.w);
    }
    int j = beg + q;
    int s0 = (j < end) ? g_srcs[j] : -1;
    int s1 = (j + 4 < end) ? g_srcs[j + 4] : -1;
    while (j < end) {
        int jn = j + 8;
        int t0 = (jn < end) ? g_srcs[jn] : -1;
        int t1 = (jn + 4 < end) ? g_srcs[jn + 4] : -1;
        if (s0 >= 0) {
            uint4 v = rows[s0 * 8 + r];
            a0 = add2(a0, h2f2(v.x));
            a1 = add2(a1, h2f2(v.y));
            a2 = add2(a2, h2f2(v.z));
            a3 = add2(a3, h2f2(v.w));
        }
        if (s1 >= 0) {
            uint4 v = rows[s1 * 8 + r];
            b0 = add2(b0, h2f2(v.x));
            b1 = add2(b1, h2f2(v.y));
            b2 = add2(b2, h2f2(v.z));
            b3 = add2(b3, h2f2(v.w));
        }
        s0 = t0; s1 = t1; j = jn;
    }
    a0 = add2(a0, b0); a1 = add2(a1, b1); a2 = add2(a2, b2); a3 = add2(a3, b3);
    a0 = add2(a0, shfl_dn64(a0, 16));
    a1 = add2(a1, shfl_dn64(a1, 16));
    a2 = add2(a2, shfl_dn64(a2, 16));
    a3 = add2(a3, shfl_dn64(a3, 16));
    a0 = add2(a0, shfl_dn64(a0, 8));
    a1 = add2(a1, shfl_dn64(a1, 8));
    a2 = add2(a2, shfl_dn64(a2, 8));
    a3 = add2(a3, shfl_dn64(a3, 8));
    if (q == 0) {
        float2 f0 = upk(a0), f1 = upk(a1), f2 = upk(a2), f3 = upk(a3);
        uint4 o;
        o.x = f22h2(f0.x, f0.y);
        o.y = f22h2(f1.x, f1.y);
        o.z = f22h2(f2.x, f2.y);
        o.w = f22h2(f3.x, f3.y);
        *reinterpret_cast<uint4*>(&g_aggh[w * 64 + r * 8]) = o;
    }
}

// ---------------- HMMA MLP + fused BN-stat reduce ----------------
// 128 threads = 4 warps; block = 64 nodes; warp w owns rows 16w..16w+15.
template <int KS1>
__global__ __launch_bounds__(128) void k_mlp_hmma(const float* __restrict__ W1f,
                                                  const float* __restrict__ b1,
                                                  const float* __restrict__ W2f,
                                                  const float* __restrict__ b2,
                                                  int si) {
    __shared__ __half sA[64][WPITCH];
    __shared__ __half sW1[64][WPITCH];
    __shared__ __half sW2[64][WPITCH];

    const int tid = threadIdx.x;
    const int m0 = blockIdx.x * 64;

    // load A tile (fp16 agg)
    if (KS1 == 4) {
        for (int i = tid; i < 512; i += 128) {       // 64 rows x 8 uint4
            int r = i >> 3, c = i & 7;
            uint4 v = make_uint4(0, 0, 0, 0);
            if (m0 + r < NN) v = *reinterpret_cast<const uint4*>(&g_aggh[(m0 + r) * 64 + c * 8]);
            *reinterpret_cast<uint4*>(&sA[r][c * 8]) = v;
        }
    } else {
        for (int i = tid; i < 128; i += 128) {       // 64 rows x 2 uint4 (16 halves)
            int r = i >> 1, c = i & 1;
            uint4 v = make_uint4(0, 0, 0, 0);
            if (m0 + r < NN) v = *reinterpret_cast<const uint4*>(&g_aggh[(m0 + r) * 16 + c * 8]);
            *reinterpret_cast<uint4*>(&sA[r][c * 8]) = v;
        }
    }
    // load W1
    if (KS1 == 1) {
        for (int i = tid; i < 128; i += 128) {       // 16 rows x 8 uint4, already fp16
            int r = i >> 3, c = i & 7;
            *reinterpret_cast<uint4*>(&sW1[r][c * 8]) =
                *reinterpret_cast<const uint4*>(&g_w1ph[r * 64 + c * 8]);
        }
    } else {
        for (int i = tid; i < 1024; i += 128) {
            int r = i >> 4, c = i & 15;
            float4 v = *reinterpret_cast<const float4*>(&W1f[r * 64 + c * 4]);
            *reinterpret_cast<unsigned*>(&sW1[r][c * 4]) = f22h2(v.x, v.y);
            *reinterpret_cast<unsigned*>(&sW1[r][c * 4 + 2]) = f22h2(v.z, v.w);
        }
    }
    // load W2 (64x64 fp32 -> fp16)
    for (int i = tid; i < 1024; i += 128) {
        int r = i >> 4, c = i & 15;
        float4 v = *reinterpret_cast<const float4*>(&W2f[r * 64 + c * 4]);
        *reinterpret_cast<unsigned*>(&sW2[r][c * 4]) = f22h2(v.x, v.y);
        *reinterpret_cast<unsigned*>(&sW2[r][c * 4 + 2]) = f22h2(v.z, v.w);
    }
    __syncthreads();

    const int lane = tid & 31, w = tid >> 5;
    const int g = lane >> 2, tg = lane & 3;
    const int rowA = w * 16;

    // stage 1: C1[16x64] = A[16xK] @ W1[Kx64]
    float c1[8][4];
    #pragma unroll
    for (int j = 0; j < 8; j++)
        #pragma unroll
        for (int k = 0; k < 4; k++) c1[j][k] = 0.f;

    #pragma unroll
    for (int s = 0; s < KS1; s++) {
        unsigned a[4];
        ldsm_x4(a, sptr(&sA[rowA + (lane & 15)][s * 16 + (lane >> 4) * 8]));
        #pragma unroll
        for (int j = 0; j < 8; j++) {
            unsigned b[2];
            ldsm_x2t(b, sptr(&sW1[s * 16 + (lane & 15)][j * 8]));
            mma16816(c1[j], a, b);
        }
    }
    // bias + ReLU (C layout: rows g/g+8, cols j*8+tg*2+{0,1})
    #pragma unroll
    for (int j = 0; j < 8; j++) {
        float2 bb = *reinterpret_cast<const float2*>(&b1[j * 8 + tg * 2]);
        c1[j][0] = fmaxf(c1[j][0] + bb.x, 0.f);
        c1[j][1] = fmaxf(c1[j][1] + bb.y, 0.f);
        c1[j][2] = fmaxf(c1[j][2] + bb.x, 0.f);
        c1[j][3] = fmaxf(c1[j][3] + bb.y, 0.f);
    }

    // stage 2: C2 = T @ W2; A-frags built in-register from c1
    float c2[8][4];
    #pragma unroll
    for (int j = 0; j < 8; j++)
        #pragma unroll
        for (int k = 0; k < 4; k++) c2[j][k] = 0.f;

    #pragma unroll
    for (int s = 0; s < 4; s++) {
        unsigned a2[4];
        a2[0] = f22h2(c1[2 * s][0], c1[2 * s][1]);
        a2[1] = f22h2(c1[2 * s][2], c1[2 * s][3]);
        a2[2] = f22h2(c1[2 * s + 1][0], c1[2 * s + 1][1]);
        a2[3] = f22h2(c1[2 * s + 1][2], c1[2 * s + 1][3]);
        #pragma unroll
        for (int j = 0; j < 8; j++) {
            unsigned b[2];
            ldsm_x2t(b, sptr(&sW2[s * 16 + (lane & 15)][j * 8]));
            mma16816(c2[j], a2, b);
        }
    }

    // epilogue: +b2, store h (fp32), accumulate per-column stat partials
    int r0 = m0 + rowA + g;
    int r1 = r0 + 8;
    bool v0 = (r0 < NN), v1 = (r1 < NN);
    float s2[8][2], q2[8][2];
    #pragma unroll
    for (int j = 0; j < 8; j++) {
        float2 bb = *reinterpret_cast<const float2*>(&b2[j * 8 + tg * 2]);
        int col = j * 8 + tg * 2;
        float h00 = c2[j][0] + bb.x, h01 = c2[j][1] + bb.y;
        float h10 = c2[j][2] + bb.x, h11 = c2[j][3] + bb.y;
        if (v0) *reinterpret_cast<float2*>(&g_h[r0 * 64 + col]) = make_float2(h00, h01);
        if (v1) *reinterpret_cast<float2*>(&g_h[r1 * 64 + col]) = make_float2(h10, h11);
        float a0 = v0 ? h00 : 0.f, a1 = v0 ? h01 : 0.f;
        float b0 = v1 ? h10 : 0.f, b1c = v1 ? h11 : 0.f;
        s2[j][0] = a0 + b0;
        s2[j][1] = a1 + b1c;
        q2[j][0] = a0 * a0 + b0 * b0;
        q2[j][1] = a1 * a1 + b1c * b1c;
    }
    // reduce over g (lanes stride 4, preserving tg)
    #pragma unroll
    for (int off = 16; off >= 4; off >>= 1) {
        #pragma unroll
        for (int j = 0; j < 8; j++) {
            s2[j][0] += __shfl_down_sync(0xffffffffu, s2[j][0], off);
            s2[j][1] += __shfl_down_sync(0xffffffffu, s2[j][1], off);
            q2[j][0] += __shfl_down_sync(0xffffffffu, q2[j][0], off);
            q2[j][1] += __shfl_down_sync(0xffffffffu, q2[j][1], off);
        }
    }
    __syncthreads();   // all warps done with sA/sW1/sW2 -> reuse as stat scratch
    float* sS = reinterpret_cast<float*>(sA);        // [64 cols][4 warps]
    float* sQ = sS + 256;
    if (g == 0) {
        #pragma unroll
        for (int j = 0; j < 8; j++) {
            int col = j * 8 + tg * 2;
            sS[col * 4 + w] = s2[j][0];
            sS[(col + 1) * 4 + w] = s2[j][1];
            sQ[col * 4 + w] = q2[j][0];
            sQ[(col + 1) * 4 + w] = q2[j][1];
        }
    }
    __syncthreads();
    if (tid < 64) {
        float a = sS[tid * 4] + sS[tid * 4 + 1] + sS[tid * 4 + 2] + sS[tid * 4 + 3];
        float b = sQ[tid * 4] + sQ[tid * 4 + 1] + sQ[tid * 4 + 2] + sQ[tid * 4 + 3];
        atomicAdd(&g_stats[si + tid], a);
        atomicAdd(&g_stats[si + 64 + tid], b);
    }
}

// ---------------- BN apply + ReLU -> fp16 store (optionally fused pool scatter) ----------------
template <bool POOL>
__global__ void k_bn(const float* __restrict__ gamma, const float* __restrict__ beta,
                     const int* __restrict__ batch, int si) {
    int idx = blockIdx.x * blockDim.x + threadIdx.x;
    if (idx >= NN * 16) return;
    int n = idx >> 4;
    int f0 = (idx & 15) * 4;
    const float inv = 1.0f / (float)NN;
    const float* st = g_stats + si;

    float4 hv = *reinterpret_cast<const float4*>(&g_h[n * 64 + f0]);
    float4 o;
    {
        float mu = st[f0 + 0] * inv;
        float var = st[64 + f0 + 0] * inv - mu * mu;
        o.x = fmaxf((hv.x - mu) * rsqrtf(var + BN_EPS) * gamma[f0 + 0] + beta[f0 + 0], 0.f);
    }
    {
        float mu = st[f0 + 1] * inv;
        float var = st[64 + f0 + 1] * inv - mu * mu;
        o.y = fmaxf((hv.y - mu) * rsqrtf(var + BN_EPS) * gamma[f0 + 1] + beta[f0 + 1], 0.f);
    }
    {
        float mu = st[f0 + 2] * inv;
        float var = st[64 + f0 + 2] * inv - mu * mu;
        o.z = fmaxf((hv.z - mu) * rsqrtf(var + BN_EPS) * gamma[f0 + 2] + beta[f0 + 2], 0.f);
    }
    {
        float mu = st[f0 + 3] * inv;
        float var = st[64 + f0 + 3] * inv - mu * mu;
        o.w = fmaxf((hv.w - mu) * rsqrtf(var + BN_EPS) * gamma[f0 + 3] + beta[f0 + 3], 0.f);
    }
    uint2 pk;
    pk.x = f22h2(o.x, o.y);
    pk.y = f22h2(o.z, o.w);
    *reinterpret_cast<uint2*>(&g_xh[n * 64 + f0]) = pk;
    if (POOL) {
        int g = batch[n];
        red_add_v4(&g_pool[g * 64 + f0], o);
    }
}

// ---------------- final projection ----------------
__global__ void k_out(const float* __restrict__ wout, const float* __restrict__ bout,
                      float* __restrict__ out) {
    __shared__ float mean[64];
    int g = blockIdx.x, f = threadIdx.x;
    float c = g_cnt[g];
    float sum = g_pool[g * 64 + f];
    mean[f] = (c > 0.f) ? sum / fmaxf(c, 1.f) : 0.f;
    __syncthreads();
    float acc = bout[f];
    #pragma unroll 8
    for (int k = 0; k < 64; k++) acc += mean[k] * wout[k * 64 + f];
    out[g * 64 + f] = acc;
}

// ---------------- launcher ----------------
extern "C" void kernel_launch(void* const* d_in, const int* in_sizes, int n_in,
                              void* d_out, int out_size) {
    const float* x     = (const float*)d_in[0];
    const int*   ei    = (const int*)d_in[1];
    const int*   batch = (const int*)d_in[2];
    const float* w1_0  = (const float*)d_in[3];
    const float* w1_r  = (const float*)d_in[4];
    const float* b1    = (const float*)d_in[5];
    const float* w2    = (const float*)d_in[6];
    const float* b2    = (const float*)d_in[7];
    const float* gamma = (const float*)d_in[8];
    const float* beta  = (const float*)d_in[9];
    const float* wout  = (const float*)d_in[10];
    const float* bout  = (const float*)d_in[11];
    float* out = (float*)d_out;

    const int TPB = 256;
    const int nodeBlocks  = (NN + TPB - 1) / TPB;        // 391
    const int mlpBlocks   = (NN + 63) / 64;              // 1563
    const int bnBlocks    = (NN * 16 + TPB - 1) / TPB;   // 6250
    const int edgeBlocks  = (EE + TPB - 1) / TPB;        // 12500
    const int warpBlocks  = (NN * 32 + TPB - 1) / TPB;   // 12500 (warp per node)

    // init + bucket fill
    k_init<<<nodeBlocks, TPB>>>(w1_0);
    k_prep<<<nodeBlocks, TPB>>>(x, batch);
    k_scatter<<<edgeBlocks, TPB>>>(ei);

    // ---- layer 0 (K padded 4->16) ----
    k_gather4<<<warpBlocks, TPB>>>();
    k_mlp_hmma<1><<<mlpBlocks, 128>>>(nullptr, b1 + 0, w2 + 0, b2 + 0, 0);
    k_bn<false><<<bnBlocks, TPB>>>(gamma + 0, beta + 0, nullptr, 0);

    // ---- layer 1 ----
    k_gather64<<<warpBlocks, TPB>>>();
    k_mlp_hmma<4><<<mlpBlocks, 128>>>(w1_r, b1 + 64, w2 + 4096, b2 + 64, 128);
    k_bn<false><<<bnBlocks, TPB>>>(gamma + 64, beta + 64, nullptr, 128);

    // ---- layer 2 (fuse pool into BN apply) ----
    k_gather64<<<warpBlocks, TPB>>>();
    k_mlp_hmma<4><<<mlpBlocks, 128>>>(w1_r + 4096, b1 + 128, w2 + 8192, b2 + 128, 256);
    k_bn<true><<<bnBlocks, TPB>>>(gamma + 128, beta + 128, batch, 256);

    // ---- output projection ----
    k_out<<<GG, 64>>>(wout, bout, out);
}